// round 16
// baseline (speedup 1.0000x reference)
#include <cuda_runtime.h>
#include <cstdint>

#define SEQ   4096
#define BATCH 64
#define DIM   96
#define HID   128
#define NROWS (SEQ*BATCH)
#define NGC   16                  // gemm-role CTAs per fused kernel
#define NPAIR 8192                // 2048 m-blocks x 4 n-pairs

using u64 = unsigned long long;

// ---------------- scratch (static device globals) ---------------------------
__device__ float g_zx0[(size_t)NROWS*1024 + 65536];  // [row=t*64+b][n], +1 step pad
__device__ float g_zx1[(size_t)NROWS*1024 + 65536];
__device__ float g_ys0[(size_t)NROWS*256];           // [t][b][2H]
__device__ float g_ys1[(size_t)NROWS*256];
__device__ int   g_prog[2][NGC];                     // gemm progress (next pair idx)

// ---------------- helpers ----------------------------------------------------
__device__ __forceinline__ float sigm(float x)   { return 1.f/(1.f+__expf(-x)); }
__device__ __forceinline__ float tanha(float x)  {
    float r; asm("tanh.approx.f32 %0, %1;" : "=f"(r) : "f"(x)); return r;
}
__device__ __forceinline__ float sigma_fast(float x) {
    return fmaf(0.5f, tanha(0.5f*x), 0.5f);
}
__device__ __forceinline__ void ffma2(u64 &d, u64 a, u64 b) {
    asm volatile("fma.rn.f32x2 %0, %1, %2, %0;" : "+l"(d) : "l"(a), "l"(b));
}
__device__ __forceinline__ void lds2(u64 &a, u64 &b, uint32_t addr) {
    asm volatile("ld.shared.v2.u64 {%0,%1}, [%2];" : "=l"(a), "=l"(b) : "r"(addr));
}
__device__ __forceinline__ void unpk(float &lo, float &hi, u64 v) {
    asm volatile("mov.b64 {%0,%1}, %2;" : "=f"(lo), "=f"(hi) : "l"(v));
}
__device__ __forceinline__ void cpasync16(uint32_t dst, const void* src) {
    asm volatile("cp.async.ca.shared.global [%0], [%1], 16;" :: "r"(dst), "l"(src));
}
__device__ __forceinline__ int ldacq(const int* p) {
    int v; asm volatile("ld.acquire.gpu.global.s32 %0, [%1];" : "=r"(v) : "l"(p) : "memory"); return v;
}
__device__ __forceinline__ void strel(int* p, int v) {
    asm volatile("st.release.gpu.global.s32 [%0], %1;" :: "l"(p), "r"(v) : "memory");
}
__device__ __forceinline__ void mma_tf32(float4 &c,
    uint32_t a0, uint32_t a1, uint32_t a2, uint32_t a3,
    uint32_t b0, uint32_t b1)
{
    asm volatile("mma.sync.aligned.m16n8k8.row.col.f32.tf32.tf32.f32 "
        "{%0,%1,%2,%3}, {%4,%5,%6,%7}, {%8,%9}, {%0,%1,%2,%3};"
        : "+f"(c.x), "+f"(c.y), "+f"(c.z), "+f"(c.w)
        : "r"(a0), "r"(a1), "r"(a2), "r"(a3), "r"(b0), "r"(b1));
}

__global__ void init_kernel() {
    int tid = threadIdx.x;
    if (tid < 2*NGC) ((int*)g_prog)[tid] = 0;
}

// ---------------- fused kernel: 128 recur CTAs + 16 gemm CTAs ----------------
// gemm-role: dual half-tile cp.async GEMM over static pair partition in
// t-ascending order; publishes progress (release). recur-role: R15 quarter-
// split recurrence, gated every 8 steps on min(progress) (acquire + barrier).
// smem: gemm: As[2][4608] + Ws[2 half][2 stg][4608] = 110592 B
//       recur: wsm 65536 + hs 1280  (union; kernel smem = 110592)
#define FSMEM (6*4608*4)

template<int LAYER, int K>
__global__ void __launch_bounds__(512, 1) fused_kernel(
    const float* __restrict__ Aext,
    const float* __restrict__ Wf, const float* __restrict__ Wb,
    const float* __restrict__ bf, const float* __restrict__ bb,
    const float* __restrict__ whhf, const float* __restrict__ whhb)
{
    extern __shared__ char smraw[];
    const int bid = blockIdx.x;
    const int tid = threadIdx.x;

    if (bid >= 128) {
        // ================= gemm role =================
        const int id   = bid - 128;            // 0..NGC-1
        const int half = tid >> 8;             // 0/1: two tiles per CTA
        const int htid = tid & 255;
        uint32_t* As  = (uint32_t*)smraw;                       // [2][4608] shared
        uint32_t* Wsm = (uint32_t*)smraw + 2*4608 + half*2*4608;// [2][4608] per half

        const float* A = LAYER ? (const float*)g_ys0 : Aext;
        float*       Z = LAYER ? g_zx1 : g_zx0;

        const int wid = htid >> 5, lane = htid & 31;
        const int wm  = wid & 3,   wn   = wid >> 2;
        const int g   = lane >> 2, t4   = lane & 3;

        uint32_t as_s = (uint32_t)__cvta_generic_to_shared(As);
        uint32_t ws_s = (uint32_t)__cvta_generic_to_shared(Wsm);
        const int NT = K / 32;

        for (int pp = id; pp < NPAIR; pp += NGC) {
            const int m0 = (pp >> 2) * 128;
            const int n0 = ((pp & 3)*2 + half) * 128;
            const float* W    = (n0 < 512) ? (Wf + (size_t)n0*K) : (Wb + (size_t)(n0-512)*K);
            const float* bias = (n0 < 512) ? (bf + n0) : (bb + (n0-512));

            float4 acc[2][8];
#pragma unroll
            for (int mi = 0; mi < 2; mi++)
#pragma unroll
                for (int ni = 0; ni < 8; ni++) acc[mi][ni] = make_float4(0.f,0.f,0.f,0.f);

            auto prefetch = [&](int kt, int stg) {
                int k0 = kt * 32;
#pragma unroll
                for (int i = 0; i < 2; i++) {             // As: 1024 f4 by 512 thr
                    int q = tid + i*512, r = q >> 3, kq = q & 7;
                    cpasync16(as_s + (stg*4608 + r*36 + kq*4)*4,
                              A + (size_t)(m0+r)*K + k0 + kq*4);
                }
#pragma unroll
                for (int i = 0; i < 4; i++) {             // Ws: 1024 f4 by 256 thr
                    int q = htid + i*256, r = q >> 3, kq = q & 7;
                    cpasync16(ws_s + (stg*4608 + r*36 + kq*4)*4,
                              W + (size_t)r*K + k0 + kq*4);
                }
                asm volatile("cp.async.commit_group;" ::: "memory");
            };

            prefetch(0, 0);
            for (int kt = 0; kt < NT; kt++) {
                if (kt + 1 < NT) {
                    prefetch(kt + 1, (kt + 1) & 1);
                    asm volatile("cp.async.wait_group 1;" ::: "memory");
                } else {
                    asm volatile("cp.async.wait_group 0;" ::: "memory");
                }
                __syncthreads();

                const uint32_t* Ast = As  + (kt & 1)*4608;
                const uint32_t* Wst = Wsm + (kt & 1)*4608;
#pragma unroll
                for (int kb = 0; kb < 32; kb += 8) {
                    uint32_t a[2][4];
#pragma unroll
                    for (int mi = 0; mi < 2; mi++) {
                        int R = wm*32 + mi*16;
                        a[mi][0] = Ast[(R + g    )*36 + kb + t4    ];
                        a[mi][1] = Ast[(R + g + 8)*36 + kb + t4    ];
                        a[mi][2] = Ast[(R + g    )*36 + kb + t4 + 4];
                        a[mi][3] = Ast[(R + g + 8)*36 + kb + t4 + 4];
                    }
#pragma unroll
                    for (int ni = 0; ni < 8; ni++) {
                        int N8 = wn*64 + ni*8;
                        uint32_t b0 = Wst[(N8 + g)*36 + kb + t4    ];
                        uint32_t b1 = Wst[(N8 + g)*36 + kb + t4 + 4];
                        mma_tf32(acc[0][ni], a[0][0], a[0][1], a[0][2], a[0][3], b0, b1);
                        mma_tf32(acc[1][ni], a[1][0], a[1][1], a[1][2], a[1][3], b0, b1);
                    }
                }
                __syncthreads();
            }

#pragma unroll
            for (int ni = 0; ni < 8; ni++) {
                int ncl = wn*64 + ni*8 + 2*t4;
                float2 bv = *(const float2*)(bias + ncl);
#pragma unroll
                for (int mi = 0; mi < 2; mi++) {
                    float4 cf = acc[mi][ni];
                    int r0 = m0 + wm*32 + mi*16 + g;
                    float2 o0 = { cf.x + bv.x, cf.y + bv.y };
                    float2 o1 = { cf.z + bv.x, cf.w + bv.y };
                    *(float2*)(Z + (size_t)r0*1024 + n0 + ncl)     = o0;
                    *(float2*)(Z + (size_t)(r0+8)*1024 + n0 + ncl) = o1;
                }
            }
            __syncthreads();                      // both halves' STGs done
            if (tid == 0) strel(&g_prog[LAYER][id], pp + NGC);
        }
        if (tid == 0) strel(&g_prog[LAYER][id], 0x7fffffff);
        return;
    }

    // ================= recur role (R15 quarter-split + gating) =================
    u64*   wsm = (u64*)smraw;                       // [8 p][512 tid][2]
    float* hs  = (float*)(smraw + 65536);           // [2][160] quarter-skewed

    const int w    = tid >> 5;
    const int l    = tid & 31;
    const int uoff = l & 7;
    const int q    = l >> 3;                        // k-quarter 0..3
    const int u    = w*8 + uoff;
    const int cell = bid >> 6;
    const int b    = bid & 63;
    const float* whh = cell ? whhb : whhf;
    const float* zx  = LAYER ? g_zx1 : g_zx0;
    float*       ys  = LAYER ? g_ys1 : g_ys0;

    u64 wreg[48];                                   // gates 0..2
#pragma unroll
    for (int gg = 0; gg < 3; gg++) {
        const u64* wr = (const u64*)whh + (size_t)(gg*128 + u)*64 + q*16;
#pragma unroll
        for (int p = 0; p < 16; p++) wreg[gg*16 + p] = __ldg(wr + p);
    }
    {                                               // gate 3 -> smem
        const u64* wr = (const u64*)whh + (size_t)(3*128 + u)*64 + q*16;
#pragma unroll
        for (int p = 0; p < 8; p++) {
            wsm[(p*512 + tid)*2 + 0] = __ldg(wr + 2*p);
            wsm[(p*512 + tid)*2 + 1] = __ldg(wr + 2*p + 1);
        }
    }
    if (tid < 320) hs[tid] = 0.f;

    uint32_t hs_s  = (uint32_t)__cvta_generic_to_shared(hs);
    uint32_t wsm_s = (uint32_t)__cvta_generic_to_shared(wsm);

    const float* zptr = zx + (size_t)b*1024 + cell*512 + q*128 + u;
    float* ysp = ys + (size_t)b*256 + cell*128 + u;
    float c = 0.f;
    const int hw = (u >> 5)*36 + (u & 31);
    int* prog = &g_prog[LAYER][0];

    // gate: spin until timesteps [0, need) of zx are published
    auto gate = [&](int need) {
        if (tid < 32) {
            int avail;
            do {
                int p = (tid < NGC) ? ldacq(prog + tid) : 0x7fffffff;
#pragma unroll
                for (int o = 16; o; o >>= 1) {
                    int pq = __shfl_xor_sync(0xffffffffu, p, o);
                    p = min(p, pq);
                }
                avail = 2 * (p >> 2);               // pairs -> timesteps
            } while (avail < need);
        }
        __syncthreads();
    };

    gate(9 < SEQ ? 9 : SEQ);
    float zcur = __ldcs(zptr);

    for (int t = 0; t < SEQ; t++) {
        if (t && (t & 7) == 0) {
            int need = t + 9; if (need > SEQ) need = SEQ;
            gate(need);
        }
        float znext = __ldcs(zptr + (size_t)(t+1)*65536);
        uint32_t hb = hs_s + (t & 1)*640 + q*144;

        u64 a0 = 0ull, a1 = 0ull, a2 = 0ull, a3 = 0ull;
#pragma unroll
        for (int p = 0; p < 8; p++) {
            u64 ha, hv, va, vb;
            lds2(ha, hv, hb + p*16);
            lds2(va, vb, wsm_s + (p*512 + tid)*16);
            ffma2(a0, wreg[2*p],      ha);
            ffma2(a0, wreg[2*p+1],    hv);
            ffma2(a1, wreg[16+2*p],   ha);
            ffma2(a1, wreg[16+2*p+1], hv);
            ffma2(a2, wreg[32+2*p],   ha);
            ffma2(a2, wreg[32+2*p+1], hv);
            ffma2(a3, va, ha);
            ffma2(a3, vb, hv);
        }
        float p0, p1, p2, p3;
        { float lo,hi; unpk(lo,hi,a0); p0 = lo+hi; }
        { float lo,hi; unpk(lo,hi,a1); p1 = lo+hi; }
        { float lo,hi; unpk(lo,hi,a2); p2 = lo+hi; }
        { float lo,hi; unpk(lo,hi,a3); p3 = lo+hi; }

        if      (q == 0) p0 += zcur;
        else if (q == 1) p1 += zcur;
        else if (q == 2) p2 += zcur;
        else             p3 += zcur;
        zcur = znext;

        p0 += __shfl_xor_sync(0xffffffffu, p0, 8);
        p1 += __shfl_xor_sync(0xffffffffu, p1, 8);
        p2 += __shfl_xor_sync(0xffffffffu, p2, 8);
        p3 += __shfl_xor_sync(0xffffffffu, p3, 8);
        p0 += __shfl_xor_sync(0xffffffffu, p0, 16);
        p1 += __shfl_xor_sync(0xffffffffu, p1, 16);
        p2 += __shfl_xor_sync(0xffffffffu, p2, 16);
        p3 += __shfl_xor_sync(0xffffffffu, p3, 16);

        float ig = sigma_fast(p0), fg = sigma_fast(p1);
        float gg = tanha(p2),      og = sigma_fast(p3);
        c = fg*c + ig*gg;
        float h = og * tanha(c);
        if (q == 0) {
            hs[((t+1)&1)*160 + hw] = h;
            ysp[(size_t)t*16384] = h;
        }
        __syncthreads();
    }
}

// ---------------- final FC + sigmoid ----------------------------------------
__global__ void __launch_bounds__(256) fc_kernel(
    const float* __restrict__ fcw, const float* __restrict__ fcb,
    float* __restrict__ out)
{
    int gtid = blockIdx.x*blockDim.x + threadIdx.x;
    int row = gtid >> 5, lane = gtid & 31;
    if (row >= NROWS) return;
    const float* y = g_ys1 + (size_t)row*256;
    float s = 0.f;
#pragma unroll
    for (int i = 0; i < 8; i++) s += y[lane + i*32] * __ldg(fcw + lane + i*32);
#pragma unroll
    for (int o = 16; o; o >>= 1) s += __shfl_xor_sync(0xffffffffu, s, o);
    if (lane == 0) out[row] = sigm(s + fcb[0]);
}

// ---------------- launch -----------------------------------------------------
extern "C" void kernel_launch(void* const* d_in, const int* in_sizes, int n_in,
                              void* d_out, int out_size)
{
    const float* x     = (const float*)d_in[0];
    const float* wih0f = (const float*)d_in[1];
    const float* whh0f = (const float*)d_in[2];
    const float* b0f   = (const float*)d_in[3];
    const float* wih0b = (const float*)d_in[4];
    const float* whh0b = (const float*)d_in[5];
    const float* b0b   = (const float*)d_in[6];
    const float* wih1f = (const float*)d_in[7];
    const float* whh1f = (const float*)d_in[8];
    const float* b1f   = (const float*)d_in[9];
    const float* wih1b = (const float*)d_in[10];
    const float* whh1b = (const float*)d_in[11];
    const float* b1b   = (const float*)d_in[12];
    const float* fcw   = (const float*)d_in[13];
    const float* fcb   = (const float*)d_in[14];
    float* out = (float*)d_out;

    cudaFuncSetAttribute(fused_kernel<0, 96>,
                         cudaFuncAttributeMaxDynamicSharedMemorySize, FSMEM);
    cudaFuncSetAttribute(fused_kernel<1, 256>,
                         cudaFuncAttributeMaxDynamicSharedMemorySize, FSMEM);

    init_kernel<<<1, 64>>>();
    fused_kernel<0, 96><<<144, 512, FSMEM>>>(x, wih0f, wih0b, b0f, b0b, whh0f, whh0b);
    fused_kernel<1, 256><<<144, 512, FSMEM>>>(nullptr, wih1f, wih1b, b1f, b1b, whh1f, whh1b);
    fc_kernel<<<(NROWS*32)/256, 256>>>(fcw, fcb, out);
}

// round 17
// speedup vs baseline: 1.5884x; 1.5884x over previous
#include <cuda_runtime.h>
#include <cstdint>

#define SEQ   4096
#define BATCH 64
#define DIM   96
#define HID   128
#define NROWS (SEQ*BATCH)

using u64 = unsigned long long;

// ---------------- scratch (static device globals) ---------------------------
__device__ float g_zx0[(size_t)NROWS*1024 + 65536];  // [row=t*64+b][n], +1 step pad
__device__ float g_zx1[(size_t)NROWS*1024 + 65536];
__device__ float g_ys0[(size_t)NROWS*256];           // [t][b][2H]
__device__ float g_ys1[(size_t)NROWS*256];

// ---------------- helpers ----------------------------------------------------
__device__ __forceinline__ float sigm(float x)   { return 1.f/(1.f+__expf(-x)); }
__device__ __forceinline__ float tanha(float x)  {
    float r; asm("tanh.approx.f32 %0, %1;" : "=f"(r) : "f"(x)); return r;
}
__device__ __forceinline__ float sigma_fast(float x) {
    return fmaf(0.5f, tanha(0.5f*x), 0.5f);
}
__device__ __forceinline__ void ffma2(u64 &d, u64 a, u64 b) {
    asm volatile("fma.rn.f32x2 %0, %1, %2, %0;" : "+l"(d) : "l"(a), "l"(b));
}
__device__ __forceinline__ void lds2(u64 &a, u64 &b, uint32_t addr) {
    asm volatile("ld.shared.v2.u64 {%0,%1}, [%2];" : "=l"(a), "=l"(b) : "r"(addr));
}
__device__ __forceinline__ void lds4u32(uint32_t &x, uint32_t &y, uint32_t &z,
                                        uint32_t &w, uint32_t addr) {
    asm volatile("ld.shared.v4.u32 {%0,%1,%2,%3}, [%4];"
        : "=r"(x), "=r"(y), "=r"(z), "=r"(w) : "r"(addr));
}
__device__ __forceinline__ void unpk(float &lo, float &hi, u64 v) {
    asm volatile("mov.b64 {%0,%1}, %2;" : "=f"(lo), "=f"(hi) : "l"(v));
}
__device__ __forceinline__ uint32_t pack_bf2(float lo, float hi) {
    uint32_t r; asm("cvt.rn.bf16x2.f32 %0, %1, %2;" : "=r"(r) : "f"(hi), "f"(lo));
    return r;
}
// bf16x2 (u32) -> f32x2 (u64): each f32 = bf16 << 16 (exact)
__device__ __forceinline__ u64 bf2f32x2(uint32_t v) {
    u64 r;
    asm("{ .reg .b32 lo, hi;\n\t"
        "prmt.b32 lo, %1, 0, 0x1044;\n\t"
        "prmt.b32 hi, %1, 0, 0x3244;\n\t"
        "mov.b64 %0, {lo, hi}; }" : "=l"(r) : "r"(v));
    return r;
}
__device__ __forceinline__ void cpasync16(uint32_t dst, const void* src) {
    asm volatile("cp.async.ca.shared.global [%0], [%1], 16;" :: "r"(dst), "l"(src));
}
__device__ __forceinline__ void mma_tf32(float4 &c,
    uint32_t a0, uint32_t a1, uint32_t a2, uint32_t a3,
    uint32_t b0, uint32_t b1)
{
    asm volatile("mma.sync.aligned.m16n8k8.row.col.f32.tf32.tf32.f32 "
        "{%0,%1,%2,%3}, {%4,%5,%6,%7}, {%8,%9}, {%0,%1,%2,%3};"
        : "+f"(c.x), "+f"(c.y), "+f"(c.z), "+f"(c.w)
        : "r"(a0), "r"(a1), "r"(a2), "r"(a3), "r"(b0), "r"(b1));
}

// ---------------- input-projection GEMM: R13/R15 proven ----------------------
#define GSTG 4608
#define GSMEM (4*GSTG*4)

template<int K, int LAYER>
__global__ void __launch_bounds__(256, 2) mma_gemm(
    const float* __restrict__ Aext,
    const float* __restrict__ Wf, const float* __restrict__ Wb,
    const float* __restrict__ bf, const float* __restrict__ bb)
{
    extern __shared__ uint32_t gsm[];
    uint32_t* As = gsm;
    uint32_t* Ws = gsm + 2*GSTG;

    const float* A = (LAYER == 0) ? Aext : (const float*)g_ys0;
    float*       Z = LAYER ? g_zx1 : g_zx0;

    const int n0 = blockIdx.x * 128;
    const int m0 = blockIdx.y * 128;
    const float* W    = (n0 < 512) ? (Wf + (size_t)n0*K) : (Wb + (size_t)(n0-512)*K);
    const float* bias = (n0 < 512) ? (bf + n0) : (bb + (n0-512));

    const int tid  = threadIdx.x;
    const int wid  = tid >> 5, lane = tid & 31;
    const int wm   = wid & 3,  wn   = wid >> 2;
    const int g    = lane >> 2, t   = lane & 3;
    const int ldr  = tid >> 3, ldkq = tid & 7;

    uint32_t as_s = (uint32_t)__cvta_generic_to_shared(As);
    uint32_t ws_s = (uint32_t)__cvta_generic_to_shared(Ws);

    float4 acc[2][8];
#pragma unroll
    for (int mi = 0; mi < 2; mi++)
#pragma unroll
        for (int ni = 0; ni < 8; ni++) acc[mi][ni] = make_float4(0.f,0.f,0.f,0.f);

    auto prefetch = [&](int kt, int stg) {
        int k0 = kt * 32;
#pragma unroll
        for (int i = 0; i < 4; i++) {
            int r = ldr + i*32;
            cpasync16(as_s + (stg*GSTG + r*36 + ldkq*4)*4,
                      A + (size_t)(m0+r)*K + k0 + ldkq*4);
            cpasync16(ws_s + (stg*GSTG + r*36 + ldkq*4)*4,
                      W + (size_t)r*K + k0 + ldkq*4);
        }
        asm volatile("cp.async.commit_group;" ::: "memory");
    };

    const int NT = K / 32;
    prefetch(0, 0);
    for (int kt = 0; kt < NT; kt++) {
        if (kt + 1 < NT) {
            prefetch(kt + 1, (kt + 1) & 1);
            asm volatile("cp.async.wait_group 1;" ::: "memory");
        } else {
            asm volatile("cp.async.wait_group 0;" ::: "memory");
        }
        __syncthreads();

        const uint32_t* Ast = As + (kt & 1)*GSTG;
        const uint32_t* Wst = Ws + (kt & 1)*GSTG;
#pragma unroll
        for (int kb = 0; kb < 32; kb += 8) {
            uint32_t a[2][4];
#pragma unroll
            for (int mi = 0; mi < 2; mi++) {
                int R = wm*32 + mi*16;
                a[mi][0] = Ast[(R + g    )*36 + kb + t    ];
                a[mi][1] = Ast[(R + g + 8)*36 + kb + t    ];
                a[mi][2] = Ast[(R + g    )*36 + kb + t + 4];
                a[mi][3] = Ast[(R + g + 8)*36 + kb + t + 4];
            }
#pragma unroll
            for (int ni = 0; ni < 8; ni++) {
                int N8 = wn*64 + ni*8;
                uint32_t b0 = Wst[(N8 + g)*36 + kb + t    ];
                uint32_t b1 = Wst[(N8 + g)*36 + kb + t + 4];
                mma_tf32(acc[0][ni], a[0][0], a[0][1], a[0][2], a[0][3], b0, b1);
                mma_tf32(acc[1][ni], a[1][0], a[1][1], a[1][2], a[1][3], b0, b1);
            }
        }
        __syncthreads();
    }

#pragma unroll
    for (int ni = 0; ni < 8; ni++) {
        int ncl = wn*64 + ni*8 + 2*t;
        float2 bv = *(const float2*)(bias + ncl);
#pragma unroll
        for (int mi = 0; mi < 2; mi++) {
            float4 cf = acc[mi][ni];
            int r0 = m0 + wm*32 + mi*16 + g;
            float2 o0 = { cf.x + bv.x, cf.y + bv.y };
            float2 o1 = { cf.z + bv.x, cf.w + bv.y };
            *(float2*)(Z + (size_t)r0*1024 + n0 + ncl)     = o0;
            *(float2*)(Z + (size_t)(r0+8)*1024 + n0 + ncl) = o1;
        }
    }
}

// ---------------- recurrence: quarter-split-k + bf16 gate-3 stream -----------
// 128 CTAs x 512 threads (R15 skeleton). Gates 0..2 in 48 reg pairs (f32).
// Gate 3 streamed as rounded bf16x2: [4 chunk][512 tid][uint4] -> 4 LDS.128
// per thread per step (crossbar 256/SM vs 512 for f32); unpack = 2 PRMT per
// pair (bf16<<16 is exact f32), absorbed into issue slack.
#define RSMEM (32768 + 1280)

template<int LAYER>
__global__ void __launch_bounds__(512, 1) recur_kernel(
    const float* __restrict__ whhf, const float* __restrict__ whhb)
{
    extern __shared__ char smraw[];
    uint32_t* wsmu = (uint32_t*)smraw;              // [4][512][4] bf16x2
    float*    hs   = (float*)(smraw + 32768);       // [2][160] quarter-skewed

    const int tid  = threadIdx.x;
    const int w    = tid >> 5;
    const int l    = tid & 31;
    const int uoff = l & 7;
    const int q    = l >> 3;                        // k-quarter 0..3
    const int u    = w*8 + uoff;                    // unit
    const int cell = blockIdx.x >> 6;
    const int b    = blockIdx.x & 63;
    const float* whh = cell ? whhb : whhf;
    const float* zx  = LAYER ? g_zx1 : g_zx0;
    float*       ys  = LAYER ? g_ys1 : g_ys0;

    // gates 0..2: 48 reg pairs (f32 exact)
    u64 wreg[48];
#pragma unroll
    for (int gg = 0; gg < 3; gg++) {
        const u64* wr = (const u64*)whh + (size_t)(gg*128 + u)*64 + q*16;
#pragma unroll
        for (int p = 0; p < 16; p++) wreg[gg*16 + p] = __ldg(wr + p);
    }
    // gate 3: rounded bf16x2, chunked for LDS.128
    {
        const float* wr3 = whh + (size_t)(3*128 + u)*128 + q*32;
#pragma unroll
        for (int cc = 0; cc < 4; cc++) {
            uint4 v;
            v.x = pack_bf2(__ldg(wr3 + cc*8 + 0), __ldg(wr3 + cc*8 + 1));
            v.y = pack_bf2(__ldg(wr3 + cc*8 + 2), __ldg(wr3 + cc*8 + 3));
            v.z = pack_bf2(__ldg(wr3 + cc*8 + 4), __ldg(wr3 + cc*8 + 5));
            v.w = pack_bf2(__ldg(wr3 + cc*8 + 6), __ldg(wr3 + cc*8 + 7));
            ((uint4*)wsmu)[cc*512 + tid] = v;
        }
    }
    if (tid < 320) hs[tid] = 0.f;

    uint32_t hs_s  = (uint32_t)__cvta_generic_to_shared(hs);
    uint32_t wsm_s = (uint32_t)__cvta_generic_to_shared(wsmu);

    const float* zptr = zx + (size_t)b*1024 + cell*512 + q*128 + u;
    float* ysp = ys + (size_t)b*256 + cell*128 + u;
    float zcur = __ldcs(zptr);
    float c = 0.f;
    const int hw = (u >> 5)*36 + (u & 31);

    __syncthreads();

    for (int t = 0; t < SEQ; t++) {
        float znext = __ldcs(zptr + (size_t)(t+1)*65536);
        uint32_t hb = hs_s + (t & 1)*640 + q*144;

        u64 a0 = 0ull, a1 = 0ull, a2 = 0ull, a3 = 0ull;
        uint32_t c0, c1, c2, c3;
#pragma unroll
        for (int p = 0; p < 8; p++) {
            u64 ha, hv;
            lds2(ha, hv, hb + p*16);
            if ((p & 1) == 0)
                lds4u32(c0, c1, c2, c3, wsm_s + ((p >> 1)*512 + tid)*16);
            u64 w3a = bf2f32x2((p & 1) ? c2 : c0);
            u64 w3b = bf2f32x2((p & 1) ? c3 : c1);
            ffma2(a0, wreg[2*p],      ha);
            ffma2(a0, wreg[2*p+1],    hv);
            ffma2(a1, wreg[16+2*p],   ha);
            ffma2(a1, wreg[16+2*p+1], hv);
            ffma2(a2, wreg[32+2*p],   ha);
            ffma2(a2, wreg[32+2*p+1], hv);
            ffma2(a3, w3a, ha);
            ffma2(a3, w3b, hv);
        }
        float p0, p1, p2, p3;
        { float lo,hi; unpk(lo,hi,a0); p0 = lo+hi; }
        { float lo,hi; unpk(lo,hi,a1); p1 = lo+hi; }
        { float lo,hi; unpk(lo,hi,a2); p2 = lo+hi; }
        { float lo,hi; unpk(lo,hi,a3); p3 = lo+hi; }

        if      (q == 0) p0 += zcur;
        else if (q == 1) p1 += zcur;
        else if (q == 2) p2 += zcur;
        else             p3 += zcur;
        zcur = znext;

        p0 += __shfl_xor_sync(0xffffffffu, p0, 8);
        p1 += __shfl_xor_sync(0xffffffffu, p1, 8);
        p2 += __shfl_xor_sync(0xffffffffu, p2, 8);
        p3 += __shfl_xor_sync(0xffffffffu, p3, 8);
        p0 += __shfl_xor_sync(0xffffffffu, p0, 16);
        p1 += __shfl_xor_sync(0xffffffffu, p1, 16);
        p2 += __shfl_xor_sync(0xffffffffu, p2, 16);
        p3 += __shfl_xor_sync(0xffffffffu, p3, 16);

        float ig = sigma_fast(p0), fg = sigma_fast(p1);
        float gg = tanha(p2),      og = sigma_fast(p3);
        c = fg*c + ig*gg;
        float h = og * tanha(c);
        if (q == 0) {
            hs[((t+1)&1)*160 + hw] = h;
            ysp[(size_t)t*16384] = h;
        }
        __syncthreads();
    }
}

// ---------------- final FC + sigmoid ----------------------------------------
__global__ void __launch_bounds__(256) fc_kernel(
    const float* __restrict__ fcw, const float* __restrict__ fcb,
    float* __restrict__ out)
{
    int gtid = blockIdx.x*blockDim.x + threadIdx.x;
    int row = gtid >> 5, lane = gtid & 31;
    if (row >= NROWS) return;
    const float* y = g_ys1 + (size_t)row*256;
    float s = 0.f;
#pragma unroll
    for (int i = 0; i < 8; i++) s += y[lane + i*32] * __ldg(fcw + lane + i*32);
#pragma unroll
    for (int o = 16; o; o >>= 1) s += __shfl_xor_sync(0xffffffffu, s, o);
    if (lane == 0) out[row] = sigm(s + fcb[0]);
}

// ---------------- launch -----------------------------------------------------
extern "C" void kernel_launch(void* const* d_in, const int* in_sizes, int n_in,
                              void* d_out, int out_size)
{
    const float* x     = (const float*)d_in[0];
    const float* wih0f = (const float*)d_in[1];
    const float* whh0f = (const float*)d_in[2];
    const float* b0f   = (const float*)d_in[3];
    const float* wih0b = (const float*)d_in[4];
    const float* whh0b = (const float*)d_in[5];
    const float* b0b   = (const float*)d_in[6];
    const float* wih1f = (const float*)d_in[7];
    const float* whh1f = (const float*)d_in[8];
    const float* b1f   = (const float*)d_in[9];
    const float* wih1b = (const float*)d_in[10];
    const float* whh1b = (const float*)d_in[11];
    const float* b1b   = (const float*)d_in[12];
    const float* fcw   = (const float*)d_in[13];
    const float* fcb   = (const float*)d_in[14];
    float* out = (float*)d_out;

    cudaFuncSetAttribute(mma_gemm<DIM, 0>, cudaFuncAttributeMaxDynamicSharedMemorySize, GSMEM);
    cudaFuncSetAttribute(mma_gemm<256, 1>, cudaFuncAttributeMaxDynamicSharedMemorySize, GSMEM);
    cudaFuncSetAttribute(recur_kernel<0>, cudaFuncAttributeMaxDynamicSharedMemorySize, RSMEM);
    cudaFuncSetAttribute(recur_kernel<1>, cudaFuncAttributeMaxDynamicSharedMemorySize, RSMEM);

    dim3 ggrid(8, NROWS/128);
    mma_gemm<DIM, 0><<<ggrid, 256, GSMEM>>>(x, wih0f, wih0b, b0f, b0b);
    recur_kernel<0><<<128, 512, RSMEM>>>(whh0f, whh0b);

    mma_gemm<256, 1><<<ggrid, 256, GSMEM>>>(nullptr, wih1f, wih1b, b1f, b1b);
    recur_kernel<1><<<128, 512, RSMEM>>>(whh1f, whh1b);

    fc_kernel<<<(NROWS*32)/256, 256>>>(fcw, fcb, out);
}